// round 12
// baseline (speedup 1.0000x reference)
#include <cuda_runtime.h>
#include <math.h>

#define SEQN 2048
#define PF 8
#define NBLK 128            // 0..63 scan blocks, 64..127 producer blocks
#define CH_LEN 8
#define NCHUNK 256          // SEQN / CH_LEN
#define WARM 32             // MUST be a multiple of PF (loop window alignment)
#define NSCANBLK 64
#define QPAD (4 * PF)

#define NOT_READY -1.0e30f
#define QBIAS 10.0f
#define FULLM 0xFFFFFFFFu
#define RTC 0.70710678118654752440f

// ---- device scratch (no allocations allowed) ----
__device__ float g_trig[2 * 63];            // cos,sin of w[j]/2
__device__ float g_T[16];                   // pool(3,7) transfer tensor
__device__ float g_polyA[6];                // tanh(x)=x*P(x^2) on [-1,1]
__device__ float g_polyAs[6];               // sigmoid-folded: gA[j]*4^-(j+1)
__device__ float g_polyB[8];                // tanh on [-2.085,2.085]
__device__ volatile float g_q[SEQN + QPAD]; // data+flag channel: ready iff > 5

// ---- complex helpers (prep only) ----
__device__ __forceinline__ float2 cmulf(float2 a, float2 b) {
    return make_float2(a.x * b.x - a.y * b.y, a.x * b.y + a.y * b.x);
}
__device__ __forceinline__ float2 cmuljf(float2 a, float2 b) {  // a * conj(b)
    return make_float2(a.x * b.x + a.y * b.y, a.y * b.x - a.x * b.y);
}
__device__ __forceinline__ float2 sigel(int m, int r, int c) {  // I,X,Y,Z entries
    if (m == 0) return make_float2(r == c ? 1.f : 0.f, 0.f);
    if (m == 1) return make_float2(r != c ? 1.f : 0.f, 0.f);
    if (m == 2) return make_float2(0.f, (r == 0 && c == 1) ? -1.f : ((r == 1 && c == 0) ? 1.f : 0.f));
    return make_float2(r == c ? (r == 0 ? 1.f : -1.f) : 0.f, 0.f);
}

// ---- runtime poly fits (prep only) ----
__device__ __forceinline__ void fit_g8(float vmax, float* C) {
    const float cs0 = 0.98078528f, cs1 = 0.83146961f,
                cs2 = 0.55557023f, cs3 = 0.19509032f;
    float v[8], d[8];
    v[0] = 0.5f * vmax * (1.0f + cs0);
    v[1] = 0.5f * vmax * (1.0f + cs1);
    v[2] = 0.5f * vmax * (1.0f + cs2);
    v[3] = 0.5f * vmax * (1.0f + cs3);
    v[4] = 0.5f * vmax * (1.0f - cs3);
    v[5] = 0.5f * vmax * (1.0f - cs2);
    v[6] = 0.5f * vmax * (1.0f - cs1);
    v[7] = 0.5f * vmax * (1.0f - cs0);
#pragma unroll
    for (int k = 0; k < 8; k++) {
        float x = sqrtf(v[k]);
        d[k] = tanhf(x) / x;
    }
#pragma unroll
    for (int j = 1; j < 8; j++)
#pragma unroll
        for (int k = 7; k >= 1; k--)
            if (k >= j) d[k] = (d[k] - d[k - 1]) / (v[k] - v[k - j]);
#pragma unroll
    for (int i = 0; i < 8; i++) C[i] = 0.0f;
    C[0] = d[7];
#pragma unroll
    for (int k = 6; k >= 0; k--) {
#pragma unroll
        for (int i = 7; i >= 1; i--) C[i] = C[i - 1] - v[k] * C[i];
        C[0] = d[k] - v[k] * C[0];
    }
}

__device__ __forceinline__ void fit_g6(float vmax, float* C) {
    const float cs0 = 0.96592583f, cs1 = 0.70710678f, cs2 = 0.25881905f;
    float v[6], d[6];
    v[0] = 0.5f * vmax * (1.0f + cs0);
    v[1] = 0.5f * vmax * (1.0f + cs1);
    v[2] = 0.5f * vmax * (1.0f + cs2);
    v[3] = 0.5f * vmax * (1.0f - cs2);
    v[4] = 0.5f * vmax * (1.0f - cs1);
    v[5] = 0.5f * vmax * (1.0f - cs0);
#pragma unroll
    for (int k = 0; k < 6; k++) {
        float x = sqrtf(v[k]);
        d[k] = tanhf(x) / x;
    }
#pragma unroll
    for (int j = 1; j < 6; j++)
#pragma unroll
        for (int k = 5; k >= 1; k--)
            if (k >= j) d[k] = (d[k] - d[k - 1]) / (v[k] - v[k - j]);
#pragma unroll
    for (int i = 0; i < 6; i++) C[i] = 0.0f;
    C[0] = d[5];
#pragma unroll
    for (int k = 4; k >= 0; k--) {
#pragma unroll
        for (int i = 5; i >= 1; i--) C[i] = C[i - 1] - v[k] * C[i];
        C[0] = d[k] - v[k] * C[0];
    }
}

// ============================================================
// Kernel 1: trig + sentinel init + pool transfer tensor T +
// activation polynomial tables (computed ONCE here).
// ============================================================
__global__ void prep_kernel(const float* __restrict__ w) {
    int j = blockIdx.x * blockDim.x + threadIdx.x;
    if (blockIdx.x == 0) {
        int t = threadIdx.x;
        if (t < 63) {
            float s, c;
            sincosf(0.5f * w[t], &s, &c);
            g_trig[2 * t] = c;
            g_trig[2 * t + 1] = s;
        } else if (t >= 64 && t < 80) {
            int idx = t - 64, mu = idx >> 2, nu = idx & 3;
            float c0, s0, c1, s1, c2, s2;
            sincosf(0.5f * w[33], &s0, &c0);   // pool(3,7) params k=33..35
            sincosf(0.5f * w[34], &s1, &c1);
            sincosf(0.5f * w[35], &s2, &c2);
            float2 U[4][4];
            for (int col = 0; col < 4; col++) {
                float2 u[4];
                for (int i = 0; i < 4; i++) u[i] = make_float2(i == col ? 1.f : 0.f, 0.f);
                for (int i = 0; i < 4; i++) {                    // RZ bit1 (-pi/2)
                    float ss = ((i >> 1) & 1) ? -RTC : RTC;
                    u[i] = cmulf(u[i], make_float2(RTC, ss));
                }
                { float2 tt = u[2]; u[2] = u[3]; u[3] = tt; }     // CNOT c=bit1 t=bit0
                for (int i = 0; i < 4; i++) {                    // RZ bit0 (p0)
                    float ss = (i & 1) ? s0 : -s0;
                    u[i] = cmulf(u[i], make_float2(c0, ss));
                }
                for (int i = 0; i < 2; i++) {                    // RY bit1 (p1)
                    float2 a0 = u[i], a1 = u[i + 2];
                    u[i]     = make_float2(c1 * a0.x - s1 * a1.x, c1 * a0.y - s1 * a1.y);
                    u[i + 2] = make_float2(s1 * a0.x + c1 * a1.x, s1 * a0.y + c1 * a1.y);
                }
                { float2 tt = u[1]; u[1] = u[3]; u[3] = tt; }     // CNOT c=bit0 t=bit1
                for (int i = 0; i < 2; i++) {                    // RY bit1 (p2)
                    float2 a0 = u[i], a1 = u[i + 2];
                    u[i]     = make_float2(c2 * a0.x - s2 * a1.x, c2 * a0.y - s2 * a1.y);
                    u[i + 2] = make_float2(s2 * a0.x + c2 * a1.x, s2 * a0.y + c2 * a1.y);
                }
                for (int i = 0; i < 4; i++) U[i][col] = u[i];
            }
            float2 A[4][4], Bm[4][4];
            for (int i = 0; i < 4; i++)
                for (int k = 0; k < 4; k++)
                    A[i][k] = cmulf(sigel(mu, i & 1, k & 1), sigel(nu, (i >> 1) & 1, (k >> 1) & 1));
            for (int i = 0; i < 4; i++)
                for (int k = 0; k < 4; k++) {
                    float2 acc = make_float2(0.f, 0.f);
                    for (int m = 0; m < 4; m++) {
                        float2 p = cmulf(U[i][m], A[m][k]);
                        acc.x += p.x; acc.y += p.y;
                    }
                    Bm[i][k] = acc;
                }
            float tr = 0.f;
            for (int i = 0; i < 4; i++) {
                float2 cc = make_float2(0.f, 0.f);
                for (int k = 0; k < 4; k++) {
                    float2 p = cmuljf(Bm[i][k], U[i][k]);
                    cc.x += p.x; cc.y += p.y;
                }
                tr += (i < 2) ? cc.x : -cc.x;
            }
            g_T[mu * 4 + nu] = tr;
        } else if (t == 96) {
            float gA[6], gB[8];
            fit_g6(1.0f, gA);
            fit_g8(4.35f, gB);
            float s = 0.25f;
            for (int i = 0; i < 6; i++) {
                g_polyA[i]  = gA[i];
                g_polyAs[i] = gA[i] * s;
                s *= 0.25f;
            }
            for (int i = 0; i < 8; i++) g_polyB[i] = gB[i];
        }
    }
    for (int i = j; i < SEQN + QPAD; i += gridDim.x * blockDim.x)
        g_q[i] = (i < SEQN) ? NOT_READY : QBIAS;
}

// ============================================================
// Single-thread 4-qubit (16-amp) gate machinery (CNOT = renaming).
// ============================================================
template<int B>
__device__ __forceinline__ void rz16(float (&ar)[16], float (&ai)[16], float c, float s) {
#pragma unroll
    for (int i = 0; i < 16; i++) {
        float ss = ((i >> B) & 1) ? s : -s;
        float nr = ar[i] * c - ai[i] * ss;
        ai[i] = fmaf(ar[i], ss, ai[i] * c);
        ar[i] = nr;
    }
}
template<int B>
__device__ __forceinline__ void ry16(float (&ar)[16], float (&ai)[16], float c, float s) {
#pragma unroll
    for (int i = 0; i < 16; i++)
        if (((i >> B) & 1) == 0) {
            int j = i | (1 << B);
            float r0 = ar[i], r1 = ar[j], i0 = ai[i], i1 = ai[j];
            ar[i] = fmaf(c, r0, -s * r1);  ar[j] = fmaf(s, r0, c * r1);
            ai[i] = fmaf(c, i0, -s * i1);  ai[j] = fmaf(s, i0, c * i1);
        }
}
template<int C, int T>
__device__ __forceinline__ void cx16(float (&ar)[16], float (&ai)[16]) {
#pragma unroll
    for (int i = 0; i < 16; i++)
        if ((((i >> C) & 1) == 1) && (((i >> T) & 1) == 0)) {
            int j = i | (1 << T);
            float t;
            t = ar[i]; ar[i] = ar[j]; ar[j] = t;
            t = ai[i]; ai[i] = ai[j]; ai[j] = t;
        }
}
template<int A, int B>
__device__ __forceinline__ void conv16(float (&ar)[16], float (&ai)[16], int k) {
    float c0 = g_trig[2 * k],     s0 = g_trig[2 * k + 1];
    float c1 = g_trig[2 * k + 2], s1 = g_trig[2 * k + 3];
    float c2 = g_trig[2 * k + 4], s2 = g_trig[2 * k + 5];
    rz16<B>(ar, ai, RTC, -RTC);
    cx16<B, A>(ar, ai);
    rz16<A>(ar, ai, c0, s0);
    ry16<B>(ar, ai, c1, s1);
    cx16<A, B>(ar, ai);
    ry16<B>(ar, ai, c2, s2);
    cx16<B, A>(ar, ai);
    rz16<A>(ar, ai, RTC, RTC);
}

__device__ __forceinline__ void init16(float (&ar)[16], float (&ai)[16],
                                       const float* ec, const float* es) {
    ar[0] = 1.f; ai[0] = 0.f;
    ar[1] = ec[0]; ai[1] = es[0];
#pragma unroll
    for (int i = 0; i < 2; i++) {
        ar[2 + i] = ar[i] * ec[1] - ai[i] * es[1];
        ai[2 + i] = fmaf(ar[i], es[1], ai[i] * ec[1]);
    }
#pragma unroll
    for (int i = 0; i < 4; i++) {
        ar[4 + i] = ar[i] * ec[2] - ai[i] * es[2];
        ai[4 + i] = fmaf(ar[i], es[2], ai[i] * ec[2]);
    }
#pragma unroll
    for (int i = 0; i < 8; i++) {
        ar[8 + i] = ar[i] * ec[3] - ai[i] * es[3];
        ai[8 + i] = fmaf(ar[i], es[3], ai[i] * ec[3]);
    }
}

template<int B>
__device__ __forceinline__ void rho16(const float (&ar)[16], const float (&ai)[16], float r[4]) {
    float pr = 0.f, pi = 0.f, z = 0.f;
#pragma unroll
    for (int i = 0; i < 16; i++)
        if (((i >> B) & 1) == 0) {
            int j = i | (1 << B);
            pr = fmaf(ar[i], ar[j], fmaf(ai[i], ai[j], pr));
            pi = fmaf(ai[i], ar[j], fmaf(-ar[i], ai[j], pi));
            z  = fmaf(ar[i], ar[i], fmaf(ai[i], ai[i], z));
            z  = fmaf(-ar[j], ar[j], fmaf(-ai[j], ai[j], z));
        }
    r[0] = 1.0f;
    r[1] = 0.125f * pr;
    r[2] = -0.125f * pi;
    r[3] = 0.0625f * z;
}

// ============================================================
// Sample-per-thread QCNN: two independent 4-qubit group sims,
// <Z7> = 0.25 * r3^T T r7 (exact factorization of reduced circuit).
// ============================================================
__device__ void qcnn_thread(const float* __restrict__ sentence, int s) {
    const float4 xa = *(const float4*)(sentence + s * 8);
    const float4 xb = *(const float4*)(sentence + s * 8 + 4);
    float x[8] = {xa.x, xa.y, xa.z, xa.w, xb.x, xb.y, xb.z, xb.w};
    float ec[8], es[8];
#pragma unroll
    for (int q = 0; q < 8; q++) __sincosf(2.0f * x[q], &es[q], &ec[q]);

    float ar[16], ai[16];
    float r3[4], r7[4];
    {
        float pc[4] = {ec[2], ec[3], ec[4], ec[5]};
        float ps[4] = {es[2], es[3], es[4], es[5]};
        init16(ar, ai, pc, ps);
        conv16<0, 1>(ar, ai, 3);
        conv16<2, 3>(ar, ai, 6);
        conv16<1, 2>(ar, ai, 15);
        rho16<1>(ar, ai, r3);
    }
    {
        float pc[4] = {ec[0], ec[1], ec[6], ec[7]};
        float ps[4] = {es[0], es[1], es[6], es[7]};
        init16(ar, ai, pc, ps);
        conv16<0, 1>(ar, ai, 0);
        conv16<2, 3>(ar, ai, 9);
        conv16<3, 0>(ar, ai, 21);
        rho16<3>(ar, ai, r7);
    }
    float acc = 0.f;
#pragma unroll
    for (int m = 0; m < 4; m++)
#pragma unroll
        for (int n = 0; n < 4; n++)
            acc = fmaf(g_T[m * 4 + n], r3[m] * r7[n], acc);

    g_q[s] = fmaf(0.25f, acc, QBIAS);
}

// ---- Estrin evaluators ----
__device__ __forceinline__ float estrin8(const float* K, float u) {
    float u2 = u * u;
    float u4 = u2 * u2;
    float a = fmaf(K[1], u, K[0]);
    float b = fmaf(K[3], u, K[2]);
    float c = fmaf(K[5], u, K[4]);
    float d = fmaf(K[7], u, K[6]);
    float ab = fmaf(b, u2, a);
    float cd = fmaf(d, u2, c);
    return fmaf(cd, u4, ab);
}
__device__ __forceinline__ float estrin6(const float* K, float u) {
    float u2 = u * u;
    float u4 = u2 * u2;
    float a = fmaf(K[1], u, K[0]);
    float b = fmaf(K[3], u, K[2]);
    float c = fmaf(K[5], u, K[4]);
    float ab = fmaf(b, u2, a);
    return fmaf(c, u4, ab);
}

// ============================================================
// Chunked QLSTM scan, lane=gate layout (one warp per chunk).
// WARM % PF == 0 keeps every PF-window aligned so the write
// predicate (t0 >= begin) and prefetch bounds are exact.
// ============================================================
__device__ void qlstm_scan(int chunk,
                           const float* __restrict__ Wf, const float* __restrict__ bf,
                           const float* __restrict__ Wi, const float* __restrict__ bi,
                           const float* __restrict__ Wu, const float* __restrict__ bu,
                           const float* __restrict__ Wo, const float* __restrict__ bo,
                           const float* __restrict__ thf, const float* __restrict__ thi,
                           const float* __restrict__ thu, const float* __restrict__ tho,
                           const float* __restrict__ Wt, const float* __restrict__ bt,
                           float* __restrict__ out, float4* hsrow) {
    static_assert(WARM % PF == 0, "warm-up must be PF-aligned");
    const int l = threadIdx.x & 31;
    const int g = l & 3;
    const int base = l & ~3;

    const int begin = chunk * CH_LEN;
    const int warm0raw = begin - WARM;
    const int warm0 = (warm0raw < 0) ? 0 : warm0raw;
    const int end = begin + CH_LEN;

    const float* W  = (g == 0) ? Wf  : (g == 1) ? Wi  : (g == 2) ? Wu  : Wo;
    const float* b  = (g == 0) ? bf  : (g == 1) ? bi  : (g == 2) ? bu  : bo;
    const float* th = (g == 0) ? thf : (g == 1) ? thi : (g == 2) ? thu : tho;

    float w0[4], w1[4], w2[4], w3[4], w4[4], ub[4];
#pragma unroll
    for (int qq = 0; qq < 4; qq++) {
        w0[qq] = W[qq * 5 + 0];
        w1[qq] = W[qq * 5 + 1];
        w2[qq] = W[qq * 5 + 2];
        w3[qq] = W[qq * 5 + 3];
        w4[qq] = W[qq * 5 + 4];
        ub[qq] = b[qq] + th[qq];
    }

    const bool isU = (g == 2);
    float aK[6], gB[8];
#pragma unroll
    for (int i = 0; i < 6; i++) aK[i] = isU ? g_polyA[i] : g_polyAs[i];
#pragma unroll
    for (int i = 0; i < 8; i++) gB[i] = g_polyB[i];
    const float Kc = isU ? 0.0f : 0.5f;

    // prologue: wait for first PF window
    float nq[PF];
    {
        float mn;
        do {
            mn = 1e30f;
#pragma unroll
            for (int j = 0; j < PF; j++) {
                float x = g_q[warm0 + j];
                nq[j] = x;
                mn = fminf(mn, x);
            }
        } while (mn < 5.0f);
    }

    float c0s = 0.0f, c1s = 0.0f, c2s = 0.0f, c3s = 0.0f;
    float h0 = 0.0f, h1 = 0.0f, h2 = 0.0f, h3 = 0.0f;

    for (int t0 = warm0; t0 < end; t0 += PF) {
        const bool wr = (l == 0) && (t0 >= begin);
        float pn[PF];
#pragma unroll
        for (int j = 0; j < PF; j++) pn[j] = g_q[t0 + PF + j];   // prefetch

#pragma unroll
        for (int j = 0; j < PF; j++) {
            const int t = t0 + j;
            const float qv = nq[j] - QBIAS;

            float y0 = fmaf(w2[0], h1, fmaf(w1[0], h0, fmaf(w0[0], qv, ub[0])))
                     + fmaf(w4[0], h3, w3[0] * h2);
            float y1 = fmaf(w2[1], h1, fmaf(w1[1], h0, fmaf(w0[1], qv, ub[1])))
                     + fmaf(w4[1], h3, w3[1] * h2);
            float y2 = fmaf(w2[2], h1, fmaf(w1[2], h0, fmaf(w0[2], qv, ub[2])))
                     + fmaf(w4[2], h3, w3[2] * h2);
            float y3 = fmaf(w2[3], h1, fmaf(w1[3], h0, fmaf(w0[3], qv, ub[3])))
                     + fmaf(w4[3], h3, w3[3] * h2);

            const float cz0 = __cosf(y0);
            const float cz1 = __cosf(y1);
            const float cz2 = __cosf(y2);
            const float cz3 = __cosf(y3);

            const float t23 = cz2 * cz3;
            const float z0 = cz1 * t23;
            const float z1 = cz0 * cz1;
            const float z2 = z1 * cz2;
            const float z3 = z2 * cz3;

            const float a0 = fmaf(z0, estrin6(aK, z0 * z0), Kc);
            const float a1 = fmaf(z1, estrin6(aK, z1 * z1), Kc);
            const float a2 = fmaf(z2, estrin6(aK, z2 * z2), Kc);
            const float a3 = fmaf(z3, estrin6(aK, z3 * z3), Kc);

            const float f0 = __shfl_sync(FULLM, a0, base + 0);
            const float f1 = __shfl_sync(FULLM, a1, base + 0);
            const float f2 = __shfl_sync(FULLM, a2, base + 0);
            const float f3 = __shfl_sync(FULLM, a3, base + 0);
            const float i0 = __shfl_sync(FULLM, a0, base + 1);
            const float i1 = __shfl_sync(FULLM, a1, base + 1);
            const float i2 = __shfl_sync(FULLM, a2, base + 1);
            const float i3 = __shfl_sync(FULLM, a3, base + 1);
            const float u0 = __shfl_sync(FULLM, a0, base + 2);
            const float u1 = __shfl_sync(FULLM, a1, base + 2);
            const float u2 = __shfl_sync(FULLM, a2, base + 2);
            const float u3 = __shfl_sync(FULLM, a3, base + 2);
            const float o0 = __shfl_sync(FULLM, a0, base + 3);
            const float o1 = __shfl_sync(FULLM, a1, base + 3);
            const float o2 = __shfl_sync(FULLM, a2, base + 3);
            const float o3 = __shfl_sync(FULLM, a3, base + 3);

            c0s = fmaf(f0, c0s, i0 * u0);
            c1s = fmaf(f1, c1s, i1 * u1);
            c2s = fmaf(f2, c2s, i2 * u2);
            c3s = fmaf(f3, c3s, i3 * u3);

            h0 = (o0 * c0s) * estrin8(gB, c0s * c0s);
            h1 = (o1 * c1s) * estrin8(gB, c1s * c1s);
            h2 = (o2 * c2s) * estrin8(gB, c2s * c2s);
            h3 = (o3 * c3s) * estrin8(gB, c3s * c3s);

            if (wr) hsrow[t - begin] = make_float4(h0, h1, h2, h3);
        }

        // verify prefetched window; spin only if producer behind
        float mn = pn[0];
#pragma unroll
        for (int j = 1; j < PF; j++) mn = fminf(mn, pn[j]);
        while (mn < 5.0f) {
            mn = 1e30f;
#pragma unroll
            for (int j = 0; j < PF; j++) {
                float x = g_q[t0 + PF + j];
                pn[j] = x;
                mn = fminf(mn, x);
            }
        }
#pragma unroll
        for (int j = 0; j < PF; j++) nq[j] = pn[j];
    }

    // -------- head epilogue: lane = tag, rows = this chunk --------
    __syncwarp();
    const float wt0 = Wt[l * 4 + 0];
    const float wt1 = Wt[l * 4 + 1];
    const float wt2 = Wt[l * 4 + 2];
    const float wt3 = Wt[l * 4 + 3];
    const float btv = bt[l];

#pragma unroll
    for (int r = 0; r < CH_LEN; r++) {
        float4 h = hsrow[r];
        float lg = btv;
        lg = fmaf(h.x, wt0, lg);
        lg = fmaf(h.y, wt1, lg);
        lg = fmaf(h.z, wt2, lg);
        lg = fmaf(h.w, wt3, lg);

        float m = lg;
#pragma unroll
        for (int o = 16; o; o >>= 1) m = fmaxf(m, __shfl_xor_sync(FULLM, m, o));
        float e = __expf(lg - m);
        float sum = e;
#pragma unroll
        for (int o = 16; o; o >>= 1) sum += __shfl_xor_sync(FULLM, sum, o);

        out[(begin + r) * 32 + l] = (lg - m) - __logf(sum);
    }
}

// ============================================================
// Fused kernel: 128 blocks x 128 threads.
// Blocks 0..63 = scan (4 warps = 4 chunks each);
// blocks 64..127 = producers (warp 0 = 32 samples, sample/thread).
// ============================================================
__global__ void __launch_bounds__(128, 1)
fused_kernel(const float* __restrict__ sentence,
             const float* __restrict__ Wf, const float* __restrict__ bf,
             const float* __restrict__ Wi, const float* __restrict__ bi,
             const float* __restrict__ Wu, const float* __restrict__ bu,
             const float* __restrict__ Wo, const float* __restrict__ bo,
             const float* __restrict__ thf, const float* __restrict__ thi,
             const float* __restrict__ thu, const float* __restrict__ tho,
             const float* __restrict__ Wt, const float* __restrict__ bt,
             float* __restrict__ out) {
    if (blockIdx.x < NSCANBLK) {
        __shared__ float4 hbuf[4][CH_LEN];
        const int w = threadIdx.x >> 5;
        qlstm_scan(blockIdx.x * 4 + w,
                   Wf, bf, Wi, bi, Wu, bu, Wo, bo,
                   thf, thi, thu, tho, Wt, bt, out, hbuf[w]);
        return;
    }
    const int pb = blockIdx.x - NSCANBLK;
    if (threadIdx.x < 32)
        qcnn_thread(sentence, pb * 32 + threadIdx.x);
}

// ============================================================
extern "C" void kernel_launch(void* const* d_in, const int* in_sizes, int n_in,
                              void* d_out, int out_size) {
    const float* sentence = (const float*)d_in[0];
    const float* qcnn_w   = (const float*)d_in[1];
    const float* Wf  = (const float*)d_in[2];
    const float* bf  = (const float*)d_in[3];
    const float* Wi  = (const float*)d_in[4];
    const float* bi  = (const float*)d_in[5];
    const float* Wu  = (const float*)d_in[6];
    const float* bu  = (const float*)d_in[7];
    const float* Wo  = (const float*)d_in[8];
    const float* bo  = (const float*)d_in[9];
    const float* thf = (const float*)d_in[10];
    const float* thi = (const float*)d_in[11];
    const float* thu = (const float*)d_in[12];
    const float* tho = (const float*)d_in[13];
    const float* Wt  = (const float*)d_in[14];
    const float* bt  = (const float*)d_in[15];
    float* out = (float*)d_out;

    prep_kernel<<<9, 256>>>(qcnn_w);
    fused_kernel<<<NBLK, 128>>>(sentence,
                                Wf, bf, Wi, bi, Wu, bu, Wo, bo,
                                thf, thi, thu, tho, Wt, bt, out);
}